// round 14
// baseline (speedup 1.0000x reference)
#include <cuda_runtime.h>
#include <cuda_fp16.h>
#include <cstdint>
#include <math.h>

#define NHEADS 16
#define HD     1024            /* elements per token row (16 heads x 64) */
#define LDHB   144             /* fp16 SMEM row stride in BYTES (72 halfs) */
#define COEF   0.18033688011112042f   /* log2(e)/8, folded into Q */
#define ONESH  0x3C003C00u     /* f16x2 (1.0, 1.0) */

/* SMEM: 3-stage pipeline; stage = TWO k-blocks of fp16 K+V.
   Layout per stage: [K(b0) 9216 | V(b0) 9216 | K(b1) 9216 | V(b1) 9216]. */
#define STAGE_B 36864
#define SMEM_BYTES (3 * STAGE_B)   /* 110592 B */

/* fp16 copies of K and V, produced once per launch by cvt_kv */
__device__ __half KH[4096 * 1024];
__device__ __half VH[4096 * 1024];

__device__ __forceinline__ uint32_t smem_u32(const void* p) {
    uint32_t a;
    asm("{ .reg .u64 t; cvta.to.shared.u64 t, %1; cvt.u32.u64 %0, t; }" : "=r"(a) : "l"(p));
    return a;
}
__device__ __forceinline__ uint32_t f16x2(float hi, float lo) {
    uint32_t r; asm("cvt.rn.f16x2.f32 %0, %1, %2;" : "=r"(r) : "f"(hi), "f"(lo)); return r;
}
__device__ __forceinline__ float ex2a(float x) {
    float r; asm("ex2.approx.f32 %0, %1;" : "=f"(r) : "f"(x)); return r;
}
__device__ __forceinline__ void ldsm4(uint32_t* r, uint32_t addr) {
    asm volatile("ldmatrix.sync.aligned.m8n8.x4.shared.b16 {%0,%1,%2,%3}, [%4];"
                 : "=r"(r[0]), "=r"(r[1]), "=r"(r[2]), "=r"(r[3]) : "r"(addr));
}
__device__ __forceinline__ void ldsm4t(uint32_t* r, uint32_t addr) {
    asm volatile("ldmatrix.sync.aligned.m8n8.x4.trans.shared.b16 {%0,%1,%2,%3}, [%4];"
                 : "=r"(r[0]), "=r"(r[1]), "=r"(r[2]), "=r"(r[3]) : "r"(addr));
}
__device__ __forceinline__ void mma16(float* c, const uint32_t* a, uint32_t b0, uint32_t b1) {
    asm volatile("mma.sync.aligned.m16n8k16.row.col.f32.f16.f16.f32 "
                 "{%0,%1,%2,%3}, {%4,%5,%6,%7}, {%8,%9}, {%0,%1,%2,%3};"
                 : "+f"(c[0]), "+f"(c[1]), "+f"(c[2]), "+f"(c[3])
                 : "r"(a[0]), "r"(a[1]), "r"(a[2]), "r"(a[3]), "r"(b0), "r"(b1));
}
__device__ __forceinline__ void cpa16(uint32_t dst, const void* src) {
    asm volatile("cp.async.cg.shared.global [%0], [%1], 16;" :: "r"(dst), "l"(src) : "memory");
}
#define CPA_COMMIT() asm volatile("cp.async.commit_group;" ::: "memory")
#define CPA_WAIT1()  asm volatile("cp.async.wait_group 1;" ::: "memory")

/* ---- prepass: fp32 -> fp16 copies of K and V ---- */
__global__ __launch_bounds__(256)
void cvt_kv(const float* __restrict__ kg, const float* __restrict__ vg)
{
    const size_t i = (size_t)blockIdx.x * blockDim.x + threadIdx.x;  /* float4 units */
    const float* src = blockIdx.y ? vg : kg;
    __half2* dst = reinterpret_cast<__half2*>((blockIdx.y ? VH : KH) + i * 4);
    float4 v = *reinterpret_cast<const float4*>(src + i * 4);
    dst[0] = __floats2half2_rn(v.x, v.y);
    dst[1] = __floats2half2_rn(v.z, v.w);
}

__global__ __launch_bounds__(256, 2)
void bs_attn_mma(const float* __restrict__ qg_, float* __restrict__ out)
{
    /* global LPT order: all heads' heaviest pairs first */
    const int bid = (int)blockIdx.x;
    const int pr  = 31 - (bid >> 4);
    const int h   = bid & 15;
    const int qlo = pr << 1;                  /* CTA covers q-blocks qlo, qlo+1 */

    extern __shared__ char sb[];
    const uint32_t smu = smem_u32(sb);
    const int tid  = (int)threadIdx.x;
    const int lane = tid & 31;
    const int w    = tid >> 5;                /* 8 warps, warp owns rows 16w..16w+15 */
    const int g    = lane >> 2;
    const int t    = lane & 3;
    const int l16  = lane & 15;
    const int lh   = lane >> 4;

    /* loader mapping: thread -> (token row jq, half-group dgh of 16 halfs) */
    const int jq  = tid & 63;
    const int dgh = (tid >> 6) << 4;          /* 0,16,32,48 halfs */

    /* ---- stage Q (128 rows, x COEF, fp16 rn) into stage-0 area ---- */
    #pragma unroll
    for (int e = 0; e < 8; ++e) {
        const int idx = (e << 8) + tid;       /* 2048 float4 groups */
        const int row = idx >> 4, d4 = idx & 15;
        float4 v = *reinterpret_cast<const float4*>(
            qg_ + (size_t)(qlo * 64 + row) * HD + h * 64 + (d4 << 2));
        uint2 u;
        u.x = f16x2(v.y * COEF, v.x * COEF);
        u.y = f16x2(v.w * COEF, v.z * COEF);
        *reinterpret_cast<uint2*>(sb + row * LDHB + (d4 << 3)) = u;
    }
    __syncthreads();

    uint32_t qa[16];                          /* fp16 A-frags for 4 k16-steps */
    {
        const uint32_t rbase = smu + (uint32_t)((16 * w + l16) * LDHB) + (uint32_t)(lh * 16);
        #pragma unroll
        for (int ks = 0; ks < 4; ++ks)
            ldsm4(qa + 4 * ks, rbase + ks * 32);
    }
    __syncthreads();   /* qa loaded; staging area free for cp.async */

    /* ---- k-block enumeration for the pair ---- */
    const int rv  = (7 - h) & 7;
    const int nv  = (qlo - 8 >= rv) ? (((qlo - 8 - rv) >> 3) + 1) : 0;
    const int j0  = (qlo - 7 > 0) ? (qlo - 7) : 0;
    const int nb  = nv + (qlo + 2 - j0);      /* >= 2 always */
    const int nh  = (nb + 1) >> 1;            /* stage-pairs */

    const int qbw = qlo + (w >> 2);           /* warps 0-3: qlo, 4-7: qlo+1 */
    const int rowj_off = (lh << 3) + (lane & 7);
    const int grp_half = (lane >> 3) & 1;

    #define KB_OF(i) (((i) < nv) ? (rv + ((i) << 3)) : (j0 + (i) - nv))
    /* cp.async one stage = two k-blocks of K+V (this thread's slices) */
    #define LOAD_PAIR(ip, st) do {                                                  \
        const int _i0 = (ip) << 1;                                                  \
        const int _i1 = (_i0 + 1 < nb) ? (_i0 + 1) : (nb - 1);                      \
        const int _kb0 = KB_OF(_i0), _kb1 = KB_OF(_i1);                             \
        const uint32_t _d = smu + (uint32_t)((st) * STAGE_B)                        \
                          + (uint32_t)(jq * LDHB + dgh * 2);                        \
        const __half* _k0 = KH + (size_t)(_kb0 * 64 + jq) * HD + h * 64 + dgh;      \
        const __half* _v0 = VH + (size_t)(_kb0 * 64 + jq) * HD + h * 64 + dgh;      \
        cpa16(_d, _k0);                cpa16(_d + 16, _k0 + 8);                     \
        cpa16(_d + 9216, _v0);         cpa16(_d + 9216 + 16, _v0 + 8);              \
        const __half* _k1 = KH + (size_t)(_kb1 * 64 + jq) * HD + h * 64 + dgh;      \
        const __half* _v1 = VH + (size_t)(_kb1 * 64 + jq) * HD + h * 64 + dgh;      \
        cpa16(_d + 18432, _k1);        cpa16(_d + 18432 + 16, _k1 + 8);             \
        cpa16(_d + 27648, _v1);        cpa16(_d + 27648 + 16, _v1 + 8);             \
        CPA_COMMIT();                                                               \
    } while (0)

    /* prologue: fill stages 0 and 1 */
    LOAD_PAIR(0, 0);
    { const int i1 = (1 < nh) ? 1 : 0; LOAD_PAIR(i1, 1); }

    float oacc[8][4];
    #pragma unroll
    for (int nt = 0; nt < 8; ++nt)
        #pragma unroll
        for (int c = 0; c < 4; ++c) oacc[nt][c] = 0.0f;
    float lacc[4] = {0.0f, 0.0f, 0.0f, 0.0f};

    const int r0  = 16 * w + g;
    const int ri0 = r0 & 63;

    int stage = 0;
    for (int ih = 0; ih < nh; ++ih) {
        CPA_WAIT1();       /* pair(ih) complete locally */
        __syncthreads();   /* visible + compute(ih-1) finished everywhere */

        /* issue load(ih+2) into the stage freed by compute(ih-1) */
        {
            const int ipn = (ih + 2 < nh) ? (ih + 2) : (nh - 1);
            const int s2  = (stage + 2 >= 3) ? (stage - 1) : (stage + 2);
            LOAD_PAIR(ipn, s2);
        }

        #pragma unroll
        for (int sub = 0; sub < 2; ++sub) {
            const int idx = (ih << 1) + sub;
            const int kb  = KB_OF((idx < nb) ? idx : 0);
            const bool alw = (idx < nb) && (kb <= qbw)
                           && (((qbw - kb) < 8) || ((kb & 7) == rv));
            if (!alw) continue;
            const bool diag = (kb == qbw);

            const uint32_t kbase = smu + (uint32_t)(stage * STAGE_B + sub * 18432);
            const uint32_t vbase = kbase + 9216;

            float acc[8][4];
            #pragma unroll
            for (int nt = 0; nt < 8; ++nt)
                #pragma unroll
                for (int c = 0; c < 4; ++c) acc[nt][c] = 0.0f;

            /* GEMM1 (fp16): S = (Q*COEF) @ K^T (16 rows x 64 cols) */
            #pragma unroll
            for (int ks = 0; ks < 4; ++ks) {
                uint32_t kb4[16];
                #pragma unroll
                for (int ntp = 0; ntp < 4; ++ntp)
                    ldsm4(kb4 + 4 * ntp,
                          kbase + (uint32_t)((16 * ntp + rowj_off) * LDHB)
                                + (uint32_t)(ks * 32 + grp_half * 16));
                #pragma unroll
                for (int nt = 0; nt < 8; ++nt) {
                    const int bi = 4 * (nt >> 1) + 2 * (nt & 1);
                    mma16(acc[nt], qa + 4 * ks, kb4[bi], kb4[bi + 1]);
                }
            }

            /* interleaved softmax + GEMM2, one k16-step at a time */
            #pragma unroll
            for (int ksv = 0; ksv < 4; ++ksv) {
                uint32_t pa[4];
                #pragma unroll
                for (int hf = 0; hf < 2; ++hf) {
                    const int nt  = 2 * ksv + hf;
                    const int col = 8 * nt + 2 * t;
                    float p0 = ex2a(acc[nt][0]);
                    float p1 = ex2a(acc[nt][1]);
                    float p2 = ex2a(acc[nt][2]);
                    float p3 = ex2a(acc[nt][3]);
                    if (diag) {
                        if (col     > ri0)     p0 = 0.0f;
                        if (col + 1 > ri0)     p1 = 0.0f;
                        if (col     > ri0 + 8) p2 = 0.0f;
                        if (col + 1 > ri0 + 8) p3 = 0.0f;
                    }
                    pa[2 * hf]     = f16x2(p1, p0);   /* row g   */
                    pa[2 * hf + 1] = f16x2(p3, p2);   /* row g+8 */
                }
                mma16(lacc, pa, ONESH, ONESH);        /* row-sum via ones-B */
                uint32_t vb[16];
                #pragma unroll
                for (int dp = 0; dp < 4; ++dp)
                    ldsm4t(vb + 4 * dp,
                           vbase + (uint32_t)((ksv * 16 + l16) * LDHB)
                                 + (uint32_t)(dp * 32 + lh * 16));
                #pragma unroll
                for (int nt = 0; nt < 8; ++nt) {
                    const int bi = 4 * (nt >> 1) + 2 * (nt & 1);
                    mma16(oacc[nt], pa, vb[bi], vb[bi + 1]);
                }
            }
        }

        stage = (stage + 1 >= 3) ? 0 : (stage + 1);
    }

    /* ---- finalize: lsum in lacc (all n-cols identical) ---- */
    const float inv0 = 1.0f / lacc[0];
    const float inv1 = 1.0f / lacc[2];

    float* ob0 = out + (size_t)(qlo * 64 + r0) * HD + h * 64;
    float* ob1 = ob0 + (size_t)8 * HD;
    #pragma unroll
    for (int nt = 0; nt < 8; ++nt) {
        const int col = 8 * nt + 2 * t;
        *reinterpret_cast<float2*>(ob0 + col) =
            make_float2(oacc[nt][0] * inv0, oacc[nt][1] * inv0);
        *reinterpret_cast<float2*>(ob1 + col) =
            make_float2(oacc[nt][2] * inv1, oacc[nt][3] * inv1);
    }
}

extern "C" void kernel_launch(void* const* d_in, const int* in_sizes, int n_in,
                              void* d_out, int out_size)
{
    const float* q = (const float*)d_in[0];
    const float* k = (const float*)d_in[1];
    const float* v = (const float*)d_in[2];
    /* d_in[3] = cu_seqlens_k, fixed [0, 4096] — unused */
    float* out = (float*)d_out;

    /* prepass: K,V -> fp16 (4096*1024/4 float4s per tensor) */
    dim3 cgrid(4096, 2);
    cvt_kv<<<cgrid, 256>>>(k, v);

    cudaFuncSetAttribute(bs_attn_mma,
                         cudaFuncAttributeMaxDynamicSharedMemorySize, SMEM_BYTES);
    bs_attn_mma<<<512, 256, SMEM_BYTES>>>(q, out);
}